// round 14
// baseline (speedup 1.0000x reference)
#include <cuda_runtime.h>
#include <cuda_bf16.h>
#include <cstdint>
#include <cstddef>
#include <cstdlib>
#include <cstring>
#include <cmath>
#include <dlfcn.h>
#include <unistd.h>
#include <signal.h>
#include <sys/wait.h>
#include <sys/select.h>
#include <sys/time.h>

// ---------------------------------------------------------------------------
// Problem constants
// ---------------------------------------------------------------------------
static constexpr int   DDIM     = 768;
static constexpr int   KC       = 4096;
static constexpr int   NF       = 50000;
static constexpr int   NFPAD    = 50048;    // 391 * 128
static constexpr float TEMP_INV = 1.0f / 0.07f;

// Fallback (mma.sync fp8) tiling
static constexpr int TM      = 128;
static constexpr int TN      = 128;
static constexpr int KSTEPS  = DDIM / 128;             // 6
static constexpr int NTILES  = KC / TN;                // 32
static constexpr int YS_MAIN = 8;
static constexpr int YS_CENT = 4;
static constexpr int STAGE_BYTES = 32768;
static constexpr int SMEM_TOTAL  = 3 * STAGE_BYTES;    // 98304

// tcgen05 path
static constexpr int TC_SMEM = 1024 + 12 * 16384 + 2 * 16384;   // 230400 <= 232448
static constexpr int TC_YS   = 4;

// ---------------------------------------------------------------------------
// Device scratch
// ---------------------------------------------------------------------------
__device__ __align__(16) uint8_t  g_c8 [(size_t)KC * DDIM];
__device__ __align__(16) uint8_t  g_f8 [(size_t)NFPAD * DDIM];
__device__ __align__(16) uint16_t g_cb16[(size_t)KC * DDIM];
__device__ __align__(16) uint16_t g_fb16[(size_t)NFPAD * DDIM];
__device__ float g_spart[YS_CENT * KC];
__device__ float g_s[KC];
__device__ float g_mx[YS_MAIN * NFPAD];
__device__ int   g_ma[YS_MAIN * NFPAD];
__device__ float g_J[NFPAD];

// ---------------------------------------------------------------------------
// PTX helpers (fallback path, sm_89-safe)
// ---------------------------------------------------------------------------
__device__ __forceinline__ uint32_t smem_u32(const void* p) {
    uint32_t a;
    asm("{ .reg .u64 t; cvta.to.shared.u64 t, %1; cvt.u32.u64 %0, t; }" : "=r"(a) : "l"(p));
    return a;
}
__device__ __forceinline__ void cp16(uint32_t saddr, const void* gaddr) {
    asm volatile("cp.async.cg.shared.global [%0], [%1], 16;" :: "r"(saddr), "l"(gaddr));
}
__device__ __forceinline__ void ldm_x4(uint32_t& d0, uint32_t& d1, uint32_t& d2, uint32_t& d3,
                                       uint32_t addr) {
    asm volatile("ldmatrix.sync.aligned.m8n8.x4.shared.b16 {%0,%1,%2,%3}, [%4];"
                 : "=r"(d0), "=r"(d1), "=r"(d2), "=r"(d3) : "r"(addr));
}
__device__ __forceinline__ void mma_fp8(float* c, const uint32_t* a, const uint32_t* b) {
    asm volatile(
        "mma.sync.aligned.m16n8k32.row.col.f32.e4m3.e4m3.f32 "
        "{%0,%1,%2,%3}, {%4,%5,%6,%7}, {%8,%9}, {%0,%1,%2,%3};"
        : "+f"(c[0]), "+f"(c[1]), "+f"(c[2]), "+f"(c[3])
        : "r"(a[0]), "r"(a[1]), "r"(a[2]), "r"(a[3]), "r"(b[0]), "r"(b[1]));
}
__device__ __forceinline__ uint16_t f2e4m3(float lo, float hi) {
    uint16_t r;
    asm("cvt.rn.satfinite.e4m3x2.f32 %0, %1, %2;" : "=h"(r) : "f"(hi), "f"(lo));
    return r;
}
__device__ __forceinline__ uint32_t swz(int row, int cb) {
    return (uint32_t)(row * 128 + ((cb ^ (row & 7)) << 4));
}

// ---------------------------------------------------------------------------
// normalize centroids -> bf16 or e4m3
// ---------------------------------------------------------------------------
__global__ void normalize_kernel(const float* __restrict__ cent, int use16) {
    __shared__ float red[256];
    const int r = blockIdx.x, tid = threadIdx.x;
    const float* row = cent + (size_t)r * DDIM;
    float s = 0.f;
    for (int d = tid; d < DDIM; d += 256) { float v = row[d]; s += v * v; }
    red[tid] = s;
    __syncthreads();
    for (int o = 128; o; o >>= 1) { if (tid < o) red[tid] += red[tid + o]; __syncthreads(); }
    const float inv = 1.0f / fmaxf(sqrtf(red[0]), 1e-12f);
    for (int d = tid; d < DDIM / 2; d += 256) {
        const float a = row[2 * d] * inv, b = row[2 * d + 1] * inv;
        if (use16) {
            __nv_bfloat162 p = __floats2bfloat162_rn(a, b);
            *reinterpret_cast<uint32_t*>(g_cb16 + (size_t)r * DDIM + 2 * d) =
                *reinterpret_cast<uint32_t*>(&p);
        } else {
            reinterpret_cast<uint16_t*>(g_c8 + (size_t)r * DDIM)[d] = f2e4m3(a, b);
        }
    }
}

// ---------------------------------------------------------------------------
// features fp32 -> bf16 or e4m3 (pad rows [NF, NFPAD) with zeros)
// ---------------------------------------------------------------------------
__global__ void featcvt_kernel(const float* __restrict__ f, int use16) {
    const long long idx = (long long)blockIdx.x * 256 + threadIdx.x;
    if (idx >= (long long)NFPAD * (DDIM / 4)) return;
    const long long row = idx / (DDIM / 4);
    const int d4 = (int)(idx % (DDIM / 4));
    float4 v = make_float4(0.f, 0.f, 0.f, 0.f);
    if (row < NF)
        v = *reinterpret_cast<const float4*>(f + row * DDIM + d4 * 4);
    if (use16) {
        __nv_bfloat162 p0 = __floats2bfloat162_rn(v.x, v.y);
        __nv_bfloat162 p1 = __floats2bfloat162_rn(v.z, v.w);
        *reinterpret_cast<uint2*>(g_fb16 + row * DDIM + d4 * 4) =
            make_uint2(*reinterpret_cast<uint32_t*>(&p0), *reinterpret_cast<uint32_t*>(&p1));
    } else {
        const uint32_t w8 = (uint32_t)f2e4m3(v.x, v.y) | ((uint32_t)f2e4m3(v.z, v.w) << 16);
        *reinterpret_cast<uint32_t*>(g_f8 + row * DDIM + d4 * 4) = w8;
    }
}

// ---------------------------------------------------------------------------
// Fallback fp8 GEMM (R11, passed at 1043.9 us)
// ---------------------------------------------------------------------------
#define PF()                                                                              \
    do {                                                                                  \
        if (pf < gs_total) {                                                              \
            const int p_nt = t0 + pf / KSTEPS;                                            \
            const int p_kk = pf % KSTEPS;                                                 \
            const uint32_t stg = sb + (uint32_t)(pf % 3) * STAGE_BYTES;                   \
            const uint8_t* Ag = A + (size_t)row0 * DDIM + p_kk * 128;                     \
            const uint8_t* Bg = g_c8 + (size_t)p_nt * TN * DDIM + p_kk * 128;             \
            _Pragma("unroll")                                                             \
            for (int i = 0; i < 4; i++) {                                                 \
                const int v = tid + i * 256;                                              \
                const int r = v >> 3, cb = v & 7;                                         \
                cp16(stg + swz(r, cb), Ag + (size_t)r * DDIM + cb * 16);                  \
            }                                                                             \
            _Pragma("unroll")                                                             \
            for (int i = 0; i < 4; i++) {                                                 \
                const int v = tid + i * 256;                                              \
                const int r = v >> 3, cb = v & 7;                                         \
                cp16(stg + 16384 + swz(r, cb), Bg + (size_t)r * DDIM + cb * 16);          \
            }                                                                             \
        }                                                                                 \
        asm volatile("cp.async.commit_group;" ::: "memory");                              \
        pf++;                                                                             \
    } while (0)

#define LDFRAG(kq)                                                                        \
    do {                                                                                  \
        const int cbx = (kq) * 2 + (lane >> 4);                                           \
        _Pragma("unroll")                                                                 \
        for (int i = 0; i < 4; i++) {                                                     \
            const int r = wm * 64 + i * 16 + (lane & 15);                                 \
            ldm_x4(af[i][0], af[i][1], af[i][2], af[i][3], stBase + swz(r, cbx));         \
        }                                                                                 \
        _Pragma("unroll")                                                                 \
        for (int jj = 0; jj < 2; jj++) {                                                  \
            const int r = wn * 32 + jj * 16 + (lane & 15);                                \
            uint32_t d0, d1, d2, d3;                                                      \
            ldm_x4(d0, d1, d2, d3, stBase + 16384 + swz(r, cbx));                         \
            bf[jj * 2 + 0][0] = d0; bf[jj * 2 + 1][0] = d1;                               \
            bf[jj * 2 + 0][1] = d2; bf[jj * 2 + 1][1] = d3;                               \
        }                                                                                 \
    } while (0)

template <int MODE>
__global__ void __launch_bounds__(256, 2) gemm_kernel(int ntiles_per) {
    extern __shared__ char smem[];
    const uint8_t* const A = (MODE == 0) ? g_f8 : g_c8;
    const uint32_t sb = smem_u32(smem);
    const int tid  = threadIdx.x;
    const int lane = tid & 31;
    const int wm   = (tid >> 5) >> 2;
    const int wn   = (tid >> 5) & 3;
    const int row0 = blockIdx.x * TM;
    const int t0   = blockIdx.y * ntiles_per;
    const int gs_total = ntiles_per * KSTEPS;

    float c[4][4][4];
    #pragma unroll
    for (int i = 0; i < 4; i++)
        #pragma unroll
        for (int j = 0; j < 4; j++)
            #pragma unroll
            for (int r = 0; r < 4; r++) c[i][j][r] = 0.f;

    float rm[8]; int ra[8]; float rs[8];
    #pragma unroll
    for (int q = 0; q < 8; q++) { rm[q] = -3.4e38f; ra[q] = 0; rs[q] = 0.f; }

    uint32_t af[4][4];
    uint32_t bf[4][2];

    int pf = 0;
    PF();
    PF();

    int cs = 0;
    for (int ti = 0; ti < ntiles_per; ti++) {
        const int nt = t0 + ti;
        #pragma unroll 1
        for (int kk = 0; kk < KSTEPS; kk++) {
            asm volatile("cp.async.wait_group 1;" ::: "memory");
            __syncthreads();
            const uint32_t stBase = sb + (uint32_t)cs * STAGE_BYTES;
            cs++; if (cs == 3) cs = 0;
            PF();
            #pragma unroll
            for (int kq = 0; kq < 4; kq++) {
                LDFRAG(kq);
                #pragma unroll
                for (int i = 0; i < 4; i++)
                    #pragma unroll
                    for (int j = 0; j < 4; j++)
                        mma_fp8(c[i][j], af[i], bf[j]);
            }
        }
        const int colbase = nt * TN + wn * 32 + (lane & 3) * 2;
        #pragma unroll
        for (int i = 0; i < 4; i++)
            #pragma unroll
            for (int j = 0; j < 4; j++)
                #pragma unroll
                for (int r = 0; r < 4; r++) {
                    const float v = c[i][j][r];
                    const int slot = i * 2 + (r >> 1);
                    if (MODE == 0) {
                        const int col = colbase + j * 8 + (r & 1);
                        if (v > rm[slot]) { rm[slot] = v; ra[slot] = col; }
                    } else {
                        rs[slot] += expf(v * TEMP_INV);
                    }
                    c[i][j][r] = 0.f;
                }
    }

    #pragma unroll
    for (int slot = 0; slot < 8; slot++) {
        if (MODE == 0) {
            float m = rm[slot]; int ar = ra[slot];
            #pragma unroll
            for (int o = 1; o < 4; o <<= 1) {
                const float om = __shfl_xor_sync(0xFFFFFFFFu, m, o);
                const int   oa = __shfl_xor_sync(0xFFFFFFFFu, ar, o);
                if (om > m) { m = om; ar = oa; }
            }
            rm[slot] = m; ra[slot] = ar;
        } else {
            float sum = rs[slot];
            #pragma unroll
            for (int o = 1; o < 4; o <<= 1)
                sum += __shfl_xor_sync(0xFFFFFFFFu, sum, o);
            rs[slot] = sum;
        }
    }

    __syncthreads();
    float* smax = reinterpret_cast<float*>(smem);
    int*   sarg = reinterpret_cast<int*>(smem + 2048);
    float* ssum = reinterpret_cast<float*>(smem + 4096);

    if ((lane & 3) == 0) {
        const int q = lane >> 2;
        #pragma unroll
        for (int i = 0; i < 4; i++)
            #pragma unroll
            for (int h = 0; h < 2; h++) {
                const int rl = wm * 64 + i * 16 + h * 8 + q;
                const int slot = i * 2 + h;
                if (MODE == 0) { smax[rl * 4 + wn] = rm[slot]; sarg[rl * 4 + wn] = ra[slot]; }
                else           { ssum[rl * 4 + wn] = rs[slot]; }
            }
    }
    __syncthreads();

    if (tid < TM) {
        if (MODE == 0) {
            const int row = row0 + tid;
            if (row < NF) {
                float m = smax[tid * 4 + 0]; int ar = sarg[tid * 4 + 0];
                #pragma unroll
                for (int w = 1; w < 4; w++) {
                    const float om = smax[tid * 4 + w];
                    if (om > m) { m = om; ar = sarg[tid * 4 + w]; }
                }
                g_mx[blockIdx.y * NFPAD + row] = m;
                g_ma[blockIdx.y * NFPAD + row] = ar;
            }
        } else {
            const float t = ((ssum[tid * 4 + 0] + ssum[tid * 4 + 1]) + ssum[tid * 4 + 2])
                          + ssum[tid * 4 + 3];
            g_spart[blockIdx.y * KC + row0 + tid] = t;
        }
    }
}

// ---------------------------------------------------------------------------
// combine / finalize / reduce
// ---------------------------------------------------------------------------
__global__ void combine_kernel() {
    const int i = blockIdx.x * blockDim.x + threadIdx.x;
    if (i < KC)
        g_s[i] = ((g_spart[i] + g_spart[KC + i]) + g_spart[2 * KC + i]) + g_spart[3 * KC + i];
}

__global__ void finalize_kernel(int ys) {
    const int row = blockIdx.x * 256 + threadIdx.x;
    if (row >= NF) return;
    float m = g_mx[row];
    int  ar = g_ma[row];
    for (int w = 1; w < ys; w++) {
        const float om = g_mx[w * NFPAD + row];
        if (om > m) { m = om; ar = g_ma[w * NFPAD + row]; }
    }
    const float p = expf(fminf(m * TEMP_INV, 80.f));
    g_J[row] = logf(p) - logf(p + g_s[ar]);   // fl(p+s)==p for every row -> 0
}

__global__ void reduce_kernel(float* __restrict__ out) {
    __shared__ float sm[1024];
    const int tid = threadIdx.x;
    float s = 0.f;
    for (int i = tid; i < NF; i += 1024) s += g_J[i];
    sm[tid] = s;
    __syncthreads();
    for (int o = 512; o; o >>= 1) { if (tid < o) sm[tid] += sm[tid + o]; __syncthreads(); }
    if (tid == 0) out[0] = -(sm[0] / (float)NF);
}

// ---------------------------------------------------------------------------
// tcgen05 GEMM source (NVRTC, sm_100a). Verified correct on hardware in R13.
// ---------------------------------------------------------------------------
static const char* TC_SRC = R"NVSRC(
typedef unsigned int u32;
typedef unsigned long long u64;
typedef unsigned short u16;

#define BWAIT(bar, ph) do {                                                    \
  u64 tstart = clock64(); u32 done = 0;                                        \
  while (!done && (clock64() - tstart) < 200000000ULL) {                       \
    asm volatile("{\n .reg .pred p;\n"                                         \
      " mbarrier.try_wait.parity.acquire.cta.shared::cta.b64 p, [%1], %2, 0x989680;\n" \
      " selp.b32 %0, 1, 0, p;\n}"                                              \
      : "=r"(done) : "r"(bar), "r"(ph) : "memory");                            \
  }                                                                            \
} while(0)

#define LOADB(gs) do {                                                         \
  int nt_ = t0 + (gs) / 6, st_ = (gs) % 6;                                     \
  _Pragma("unroll")                                                            \
  for (int i = 0; i < 4; i++) {                                                \
    int v = tid + i * 256;                                                     \
    int r = v >> 4, dd = (v & 15) * 8;                                         \
    xreg[i] = *(const uint4*)(Bbase + (u64)(nt_ * 64 + r) * 768 + st_ * 128 + dd); \
  }                                                                            \
} while(0)

#define STOREB(b) do {                                                         \
  _Pragma("unroll")                                                            \
  for (int i = 0; i < 4; i++) {                                                \
    int v = tid + i * 256;                                                     \
    int r = v >> 4, dd = (v & 15) * 8;                                         \
    int s2 = dd >> 6, wd = dd & 63;                                            \
    u32 off = (u32)(r * 128 + wd * 2); off ^= ((off >> 3) & 0x70u);            \
    *(uint4*)(smem + 1024 + 12 * 16384 + (b) * 16384 + s2 * 8192 + off) = xreg[i]; \
  }                                                                            \
} while(0)

extern "C" __global__ void __launch_bounds__(256,1)
tc_gemm(const u16* __restrict__ Abase, const u16* __restrict__ Bbase,
        float* out_mx, int* out_ma, float* out_sp,
        int ntiles_per, int mode, int mxstride)
{
  extern __shared__ char smem[];
  const int tid  = threadIdx.x;
  const int row0 = blockIdx.x * 128;
  const int t0   = blockIdx.y * ntiles_per;
  const int total_steps = ntiles_per * 6;

  u32 sb;
  asm("{ .reg .u64 t; cvta.to.shared.u64 t, %1; cvt.u32.u64 %0, t; }" : "=r"(sb) : "l"(smem));
  const u32 TMSLOT = sb + 0;
  const u32 EMP0 = sb + 16, EMP1 = sb + 24;
  const u32 DM0  = sb + 32, DM1  = sb + 40;
  const u32 AOFF = sb + 1024;
  const u32 BOFF = sb + 1024 + 12*16384;

  if (tid == 0) {
    asm volatile("mbarrier.init.shared.b64 [%0], 1;" :: "r"(EMP0) : "memory");
    asm volatile("mbarrier.init.shared.b64 [%0], 1;" :: "r"(EMP1) : "memory");
    asm volatile("mbarrier.init.shared.b64 [%0], 1;" :: "r"(DM0)  : "memory");
    asm volatile("mbarrier.init.shared.b64 [%0], 1;" :: "r"(DM1)  : "memory");
    asm volatile("mbarrier.arrive.shared.b64 _, [%0];" :: "r"(EMP0) : "memory");
    asm volatile("mbarrier.arrive.shared.b64 _, [%0];" :: "r"(EMP1) : "memory");
  }
  if (tid < 32) {
    asm volatile("tcgen05.alloc.cta_group::1.sync.aligned.shared::cta.b32 [%0], 128;"
                 :: "r"(TMSLOT) : "memory");
    asm volatile("tcgen05.relinquish_alloc_permit.cta_group::1.sync.aligned;" ::: "memory");
  }
  __syncthreads();
  u32 tmem;
  asm volatile("ld.shared.b32 %0, [%1];" : "=r"(tmem) : "r"(TMSLOT));

  // A preload: 128 rows x 768 bf16 -> 12 SW128 sub-tiles
  #pragma unroll 4
  for (int i = 0; i < 48; i++) {
    int v = tid + i * 256;
    int r = v / 96, c8 = v % 96;
    const u16* src = Abase + (u64)(row0 + r) * 768 + c8 * 8;
    uint4 x = *(const uint4*)src;
    int sub = c8 >> 3, wd = (c8 & 7) * 8;
    u32 off = (u32)(r * 128 + wd * 2); off ^= ((off >> 3) & 0x70u);
    *(uint4*)(smem + 1024 + sub * 16384 + off) = x;
  }
  asm volatile("fence.proxy.async.shared::cta;" ::: "memory");
  __syncthreads();

  float runMax = -3.4e38f, runSum = 0.f;
  int runArg = 0;
  int pcB0 = 0, pcB1 = 0, pcD0 = 0, pcD1 = 0;
  const u64 DBASE = (2ULL<<61)|(1ULL<<46)|(64ULL<<32)|(1ULL<<16);

  uint4 xreg[4];
  LOADB(0);
  int g = 0;

  for (int it = 0; it <= ntiles_per; it++) {
    if (it < ntiles_per) {
      const int db = it & 1;
      #pragma unroll 1
      for (int step = 0; step < 6; step++) {
        const int b = g & 1;
        {
          u32 bar = b ? EMP1 : EMP0;
          u32 ph  = (u32)((b ? pcB1 : pcB0) & 1);
          if (b) pcB1++; else pcB0++;
          BWAIT(bar, ph);
        }
        STOREB(b);
        asm volatile("fence.proxy.async.shared::cta;" ::: "memory");
        __syncthreads();
        if (tid >= 128 && tid < 160) {
          u32 is1;
          asm volatile("{\n .reg .pred p;\n elect.sync _|p, 0xFFFFFFFF;\n"
                       " selp.b32 %0, 1, 0, p;\n}" : "=r"(is1));
          if (is1) {
            #pragma unroll
            for (int ks = 0; ks < 8; ks++) {
              int ksub = ks >> 2, kk = ks & 3;
              u32 aaddr = AOFF + (u32)(step * 2 + ksub) * 16384;
              u32 baddr = BOFF + (u32)b * 16384 + (u32)ksub * 8192;
              u64 ad = (DBASE | ((u64)(aaddr >> 4) & 0x3FFFULL)) + (u64)(kk * 2);
              u64 bd = (DBASE | ((u64)(baddr >> 4) & 0x3FFFULL)) + (u64)(kk * 2);
              u32 en = (step | ks) ? 1u : 0u;
              asm volatile("{\n .reg .pred p;\n setp.ne.u32 p, %5, 0;\n"
                " tcgen05.mma.cta_group::1.kind::f16 [%0], %1, %2, %3, {%4,%4,%4,%4}, p;\n}"
                :: "r"(tmem + db * 64), "l"(ad), "l"(bd), "r"(0x08100490u), "r"(0u), "r"(en)
                : "memory");
            }
            asm volatile(
              "tcgen05.commit.cta_group::1.mbarrier::arrive::one.shared::cluster.b64 [%0];"
              :: "r"(b ? EMP1 : EMP0) : "memory");
            if (step == 5)
              asm volatile(
                "tcgen05.commit.cta_group::1.mbarrier::arrive::one.shared::cluster.b64 [%0];"
                :: "r"(db ? DM1 : DM0) : "memory");
          }
        }
        g++;
        if (g < total_steps) LOADB(g);
      }
    }
    if (it >= 1 && tid < 128) {
      const int ptile = t0 + it - 1;
      const int pdb = (it - 1) & 1;
      {
        u32 bar = pdb ? DM1 : DM0;
        u32 ph  = (u32)((pdb ? pcD1 : pcD0) & 1);
        if (pdb) pcD1++; else pcD0++;
        BWAIT(bar, ph);
      }
      asm volatile("tcgen05.fence::after_thread_sync;" ::: "memory");
      u32 r0[32], r1[32];
      asm volatile("tcgen05.ld.sync.aligned.32x32b.x32.b32 "
        "{%0,%1,%2,%3,%4,%5,%6,%7,%8,%9,%10,%11,%12,%13,%14,%15,"
        "%16,%17,%18,%19,%20,%21,%22,%23,%24,%25,%26,%27,%28,%29,%30,%31}, [%32];"
        : "=r"(r0[0]),"=r"(r0[1]),"=r"(r0[2]),"=r"(r0[3]),"=r"(r0[4]),"=r"(r0[5]),
          "=r"(r0[6]),"=r"(r0[7]),"=r"(r0[8]),"=r"(r0[9]),"=r"(r0[10]),"=r"(r0[11]),
          "=r"(r0[12]),"=r"(r0[13]),"=r"(r0[14]),"=r"(r0[15]),"=r"(r0[16]),"=r"(r0[17]),
          "=r"(r0[18]),"=r"(r0[19]),"=r"(r0[20]),"=r"(r0[21]),"=r"(r0[22]),"=r"(r0[23]),
          "=r"(r0[24]),"=r"(r0[25]),"=r"(r0[26]),"=r"(r0[27]),"=r"(r0[28]),"=r"(r0[29]),
          "=r"(r0[30]),"=r"(r0[31])
        : "r"(tmem + pdb * 64));
      asm volatile("tcgen05.ld.sync.aligned.32x32b.x32.b32 "
        "{%0,%1,%2,%3,%4,%5,%6,%7,%8,%9,%10,%11,%12,%13,%14,%15,"
        "%16,%17,%18,%19,%20,%21,%22,%23,%24,%25,%26,%27,%28,%29,%30,%31}, [%32];"
        : "=r"(r1[0]),"=r"(r1[1]),"=r"(r1[2]),"=r"(r1[3]),"=r"(r1[4]),"=r"(r1[5]),
          "=r"(r1[6]),"=r"(r1[7]),"=r"(r1[8]),"=r"(r1[9]),"=r"(r1[10]),"=r"(r1[11]),
          "=r"(r1[12]),"=r"(r1[13]),"=r"(r1[14]),"=r"(r1[15]),"=r"(r1[16]),"=r"(r1[17]),
          "=r"(r1[18]),"=r"(r1[19]),"=r"(r1[20]),"=r"(r1[21]),"=r"(r1[22]),"=r"(r1[23]),
          "=r"(r1[24]),"=r"(r1[25]),"=r"(r1[26]),"=r"(r1[27]),"=r"(r1[28]),"=r"(r1[29]),
          "=r"(r1[30]),"=r"(r1[31])
        : "r"(tmem + pdb * 64 + 32));
      asm volatile("tcgen05.wait::ld.sync.aligned;" ::: "memory");
      asm volatile("tcgen05.fence::before_thread_sync;" ::: "memory");
      const int kb = ptile * 64;
      if (mode == 0) {
        #pragma unroll
        for (int c = 0; c < 32; c++) {
          float f = __uint_as_float(r0[c]);
          if (f > runMax) { runMax = f; runArg = kb + c; }
        }
        #pragma unroll
        for (int c = 0; c < 32; c++) {
          float f = __uint_as_float(r1[c]);
          if (f > runMax) { runMax = f; runArg = kb + 32 + c; }
        }
      } else {
        #pragma unroll
        for (int c = 0; c < 32; c++) runSum += expf(__uint_as_float(r0[c]) * (1.0f/0.07f));
        #pragma unroll
        for (int c = 0; c < 32; c++) runSum += expf(__uint_as_float(r1[c]) * (1.0f/0.07f));
      }
    }
  }

  if (tid < 128) {
    if (mode == 0) {
      int row = row0 + tid;
      if (row < 50000) {
        out_mx[blockIdx.y * mxstride + row] = runMax;
        out_ma[blockIdx.y * mxstride + row] = runArg;
      }
    } else {
      out_sp[blockIdx.y * 4096 + row0 + tid] = runSum;
    }
  }
  __syncthreads();
  if (tid < 32)
    asm volatile("tcgen05.dealloc.cta_group::1.sync.aligned.b32 %0, 128;" :: "r"(tmem));
}
)NVSRC";

// ---------------------------------------------------------------------------
// Runtime tcgen05 setup: fork-isolated NVRTC compile, RUNTIME library load +
// launch (graph-capture-safe: identical stream semantics to <<< >>>).
// ---------------------------------------------------------------------------
namespace {

bool         g_use_tc = false;
cudaKernel_t g_tckern = nullptr;
void* p_fb16 = nullptr;
void* p_cb16 = nullptr;
void* p_mx   = nullptr;
void* p_ma   = nullptr;
void* p_sp   = nullptr;

// child: pure NVRTC compile, no CUDA context. Writes [size][cubin] to pipe.
void compile_child(int wfd) {
    void* hnv = dlopen("libnvrtc.so.13", RTLD_NOW);
    if (!hnv) hnv = dlopen("libnvrtc.so.12", RTLD_NOW);
    if (!hnv) hnv = dlopen("libnvrtc.so", RTLD_NOW);
    uint32_t zero = 0;
    if (!hnv) { (void)!write(wfd, &zero, 4); _exit(1); }
    typedef int (*nC)(void**, const char*, const char*, int, const char**, const char**);
    typedef int (*nP)(void*, int, const char**);
    typedef int (*nS)(void*, size_t*);
    typedef int (*nG)(void*, char*);
    nC crt = (nC)dlsym(hnv, "nvrtcCreateProgram");
    nP cmp = (nP)dlsym(hnv, "nvrtcCompileProgram");
    nS gsz = (nS)dlsym(hnv, "nvrtcGetCUBINSize");
    nG get = (nG)dlsym(hnv, "nvrtcGetCUBIN");
    if (!crt || !cmp || !gsz || !get) { (void)!write(wfd, &zero, 4); _exit(1); }
    void* prog = nullptr;
    if (crt(&prog, TC_SRC, "tc.cu", 0, nullptr, nullptr) != 0) { (void)!write(wfd, &zero, 4); _exit(1); }
    const char* opts[] = { "--gpu-architecture=sm_100a" };
    if (cmp(prog, 1, opts) != 0) { (void)!write(wfd, &zero, 4); _exit(1); }
    size_t sz = 0;
    if (gsz(prog, &sz) != 0 || sz == 0 || sz > (64u << 20)) { (void)!write(wfd, &zero, 4); _exit(1); }
    char* buf = (char*)malloc(sz);
    if (!buf || get(prog, buf) != 0) { (void)!write(wfd, &zero, 4); _exit(1); }
    uint32_t s32 = (uint32_t)sz;
    (void)!write(wfd, &s32, 4);
    size_t off = 0;
    while (off < sz) {
        ssize_t w = write(wfd, buf + off, sz - off);
        if (w <= 0) _exit(1);
        off += (size_t)w;
    }
    _exit(0);
}

ssize_t read_deadline(int fd, void* dst, size_t n, int timeout_s) {
    size_t off = 0;
    struct timeval end;
    gettimeofday(&end, nullptr);
    end.tv_sec += timeout_s;
    while (off < n) {
        struct timeval now, tv;
        gettimeofday(&now, nullptr);
        long remain = (long)(end.tv_sec - now.tv_sec);
        if (remain <= 0) return -1;
        tv.tv_sec = remain; tv.tv_usec = 0;
        fd_set rf; FD_ZERO(&rf); FD_SET(fd, &rf);
        int rc = select(fd + 1, &rf, nullptr, nullptr, &tv);
        if (rc <= 0) return -1;
        ssize_t r = read(fd, (char*)dst + off, n - off);
        if (r <= 0) return -1;
        off += (size_t)r;
    }
    return (ssize_t)off;
}

// launch the tc kernel through the RUNTIME (same capture semantics as <<< >>>)
cudaError_t tc_launch(unsigned gx, unsigned gy, void** args) {
    cudaLaunchConfig_t cfg = {};
    cfg.gridDim  = dim3(gx, gy, 1);
    cfg.blockDim = dim3(256, 1, 1);
    cfg.dynamicSmemBytes = TC_SMEM;
    cfg.stream = 0;                 // legacy stream, exactly like our <<<>>> calls
    return cudaLaunchKernelExC(&cfg, (const void*)g_tckern, args);
}

bool try_setup_tcgen05() {
    // 1) fork-isolated NVRTC compile with deadline
    int pfd[2];
    if (pipe(pfd) != 0) return false;
    pid_t pid = fork();
    if (pid < 0) { close(pfd[0]); close(pfd[1]); return false; }
    if (pid == 0) { close(pfd[0]); compile_child(pfd[1]); _exit(1); }
    close(pfd[1]);
    uint32_t sz = 0;
    char* cubin = nullptr;
    bool ok = (read_deadline(pfd[0], &sz, 4, 60) == 4) && sz > 0;
    if (ok) {
        cubin = (char*)malloc(sz);
        ok = cubin && (read_deadline(pfd[0], cubin, sz, 60) == (ssize_t)sz);
    }
    close(pfd[0]);
    kill(pid, SIGKILL);
    int st; waitpid(pid, &st, 0);
    if (!ok) return false;

    // 2) RUNTIME library load (not driver cuModule) -> cudaKernel_t
    cudaLibrary_t lib = nullptr;
    if (cudaLibraryLoadData(&lib, cubin, nullptr, nullptr, 0, nullptr, nullptr, 0)
        != cudaSuccess) return false;
    if (cudaLibraryGetKernel(&g_tckern, lib, "tc_gemm") != cudaSuccess) return false;

    // 3) max dynamic smem attribute: cuKernelSetAttribute (dlsym) or runtime
    bool attr_ok = false;
    {
        void* hcu = dlopen("libcuda.so.1", RTLD_NOW);
        if (!hcu) hcu = dlopen("libcuda.so", RTLD_NOW);
        if (hcu) {
            typedef int (*kattr_t)(int, int, void*, int);
            kattr_t ka = (kattr_t)dlsym(hcu, "cuKernelSetAttribute");
            if (ka && ka(8 /*MAX_DYNAMIC_SHARED*/, TC_SMEM, (void*)g_tckern, 0) == 0)
                attr_ok = true;
        }
        if (!attr_ok &&
            cudaFuncSetAttribute((const void*)g_tckern,
                                 cudaFuncAttributeMaxDynamicSharedMemorySize,
                                 TC_SMEM) == cudaSuccess)
            attr_ok = true;
    }
    if (!attr_ok) return false;

    // 4) multi-CTA numeric self-test through the EXACT timed launch path
    const int SM = 256, K = DDIM;
    uint16_t* hA = (uint16_t*)malloc((size_t)SM * K * 2);
    uint16_t* hB = (uint16_t*)malloc((size_t)SM * K * 2);
    float* fA = (float*)malloc((size_t)SM * K * 4);
    float* fB = (float*)malloc((size_t)SM * K * 4);
    if (!hA || !hB || !fA || !fB) return false;
    for (int i = 0; i < SM * K; i++) {
        __nv_bfloat16 v = __float2bfloat16(0.01f * (float)((i * 7 + 3) % 31 - 15));
        memcpy(&hA[i], &v, 2);
        fA[i] = __bfloat162float(v);
        __nv_bfloat16 w = __float2bfloat16(0.01f * (float)((i * 11 + 5) % 29 - 14));
        memcpy(&hB[i], &w, 2);
        fB[i] = __bfloat162float(w);
    }
    if (cudaMemcpy(p_fb16, hA, (size_t)SM * K * 2, cudaMemcpyHostToDevice) != cudaSuccess)
        return false;
    if (cudaMemcpy(p_cb16, hB, (size_t)SM * K * 2, cudaMemcpyHostToDevice) != cudaSuccess)
        return false;

    void* Ab = p_fb16; void* Bb = p_cb16;
    int ntiles = 2, mode = 0, stride = NFPAD;
    void* args[] = { &Ab, &Bb, &p_mx, &p_ma, &p_sp, &ntiles, &mode, &stride };
    if (tc_launch(2, 2, args) != cudaSuccess) return false;

    bool done = false;
    for (int i = 0; i < 4000; i++) {
        cudaError_t q = cudaStreamQuery(0);
        if (q == cudaSuccess) { done = true; break; }
        if (q != cudaErrorNotReady) return false;
        usleep(10000);
    }
    if (!done) return false;

    float* gmx = (float*)malloc(2 * (size_t)NFPAD * 4);
    int*   gma = (int*)malloc(2 * (size_t)NFPAD * 4);
    if (!gmx || !gma) return false;
    if (cudaMemcpy(gmx, p_mx, 2 * (size_t)NFPAD * 4, cudaMemcpyDeviceToHost) != cudaSuccess)
        return false;
    if (cudaMemcpy(gma, p_ma, 2 * (size_t)NFPAD * 4, cudaMemcpyDeviceToHost) != cudaSuccess)
        return false;

    for (int by = 0; by < 2; by++)
        for (int m = 0; m < SM; m++) {
            float best = -3.4e38f; int barg = 0;
            for (int n = by * 128; n < by * 128 + 128; n++) {
                float s = 0.f;
                for (int k = 0; k < K; k++) s += fA[m * K + k] * fB[n * K + k];
                if (s > best) { best = s; barg = n; }
            }
            const float gm = gmx[by * NFPAD + m];
            const int   ga = gma[by * NFPAD + m];
            if (fabsf(gm - best) > 1e-2f) return false;
            if (ga != barg) {
                if (ga < by * 128 || ga >= by * 128 + 128) return false;
                float s = 0.f;
                for (int k = 0; k < K; k++) s += fA[m * K + k] * fB[ga * K + k];
                if (fabsf(s - best) > 1e-2f) return false;
            }
        }
    free(hA); free(hB); free(fA); free(fB); free(gmx); free(gma);
    return true;
}

struct Preload {
    Preload() {
        (void)cudaGetSymbolAddress(&p_fb16, g_fb16);
        (void)cudaGetSymbolAddress(&p_cb16, g_cb16);
        (void)cudaGetSymbolAddress(&p_mx, g_mx);
        (void)cudaGetSymbolAddress(&p_ma, g_ma);
        (void)cudaGetSymbolAddress(&p_sp, g_spart);
        void* p = nullptr;
        (void)cudaGetSymbolAddress(&p, g_c8);
        (void)cudaGetSymbolAddress(&p, g_f8);
        (void)cudaGetSymbolAddress(&p, g_s);
        (void)cudaGetSymbolAddress(&p, g_J);

        cudaFuncAttributes fa;
        (void)cudaFuncGetAttributes(&fa, normalize_kernel);
        (void)cudaFuncGetAttributes(&fa, featcvt_kernel);
        (void)cudaFuncGetAttributes(&fa, gemm_kernel<0>);
        (void)cudaFuncGetAttributes(&fa, gemm_kernel<1>);
        (void)cudaFuncGetAttributes(&fa, combine_kernel);
        (void)cudaFuncGetAttributes(&fa, finalize_kernel);
        (void)cudaFuncGetAttributes(&fa, reduce_kernel);

        (void)cudaFuncSetAttribute(gemm_kernel<0>,
                                   cudaFuncAttributeMaxDynamicSharedMemorySize, SMEM_TOTAL);
        (void)cudaFuncSetAttribute(gemm_kernel<1>,
                                   cudaFuncAttributeMaxDynamicSharedMemorySize, SMEM_TOTAL);

        float* scratch = nullptr;
        (void)cudaGetSymbolAddress((void**)&scratch, g_s);
        float* fdummy = nullptr;
        (void)cudaGetSymbolAddress((void**)&fdummy, g_f8);

        normalize_kernel<<<1, 256>>>((const float*)fdummy, 0);
        featcvt_kernel<<<1, 256>>>((const float*)fdummy, 0);
        gemm_kernel<1><<<dim3(1, 1), 256, SMEM_TOTAL>>>(1);
        combine_kernel<<<1, 256>>>();
        gemm_kernel<0><<<dim3(1, 1), 256, SMEM_TOTAL>>>(1);
        finalize_kernel<<<1, 256>>>(1);
        reduce_kernel<<<1, 1024>>>(scratch);
        (void)cudaDeviceSynchronize();
        (void)cudaGetLastError();

        g_use_tc = try_setup_tcgen05();
        (void)cudaDeviceSynchronize();
        (void)cudaGetLastError();
    }
};
Preload g_preload_;
}   // namespace

// ---------------------------------------------------------------------------
// Launch
// ---------------------------------------------------------------------------
extern "C" void kernel_launch(void* const* d_in, const int* in_sizes, int n_in,
                              void* d_out, int out_size) {
    const float* features = (const float*)d_in[0];
    const float* cents    = (const float*)d_in[1];
    if (n_in >= 2 && in_sizes[0] == KC * DDIM) {
        features = (const float*)d_in[1];
        cents    = (const float*)d_in[0];
    }

    const int use16 = g_use_tc ? 1 : 0;
    normalize_kernel<<<KC, 256>>>(cents, use16);
    {
        const long long tot = (long long)NFPAD * (DDIM / 4);
        featcvt_kernel<<<(unsigned)((tot + 255) / 256), 256>>>(features, use16);
    }

    if (g_use_tc) {
        void* Ab; void* Bb = p_cb16;
        int ntiles = (KC / 64) / TC_YS;   // 16
        int mode; int stride = NFPAD;
        // centroid-centroid
        Ab = p_cb16; mode = 1;
        {
            void* args[] = { &Ab, &Bb, &p_mx, &p_ma, &p_sp, &ntiles, &mode, &stride };
            (void)tc_launch(KC / 128, TC_YS, args);
        }
        combine_kernel<<<16, 256>>>();
        // main GEMM
        Ab = p_fb16; mode = 0;
        {
            void* args[] = { &Ab, &Bb, &p_mx, &p_ma, &p_sp, &ntiles, &mode, &stride };
            (void)tc_launch(NFPAD / 128, TC_YS, args);
        }
        finalize_kernel<<<(NF + 255) / 256, 256>>>(TC_YS);
    } else {
        gemm_kernel<1><<<dim3(KC / TM, YS_CENT), 256, SMEM_TOTAL>>>(NTILES / YS_CENT);
        combine_kernel<<<16, 256>>>();
        gemm_kernel<0><<<dim3(NFPAD / TM, YS_MAIN), 256, SMEM_TOTAL>>>(NTILES / YS_MAIN);
        finalize_kernel<<<(NF + 255) / 256, 256>>>(YS_MAIN);
    }
    reduce_kernel<<<1, 1024>>>((float*)d_out);
}